// round 17
// baseline (speedup 1.0000x reference)
#include <cuda_runtime.h>
#include <cuda_bf16.h>
#include <cstdint>

typedef unsigned long long u64;

#define Bb 32
#define Tt 512
#define Dd 512
#define Hh 1024
#define Gg 4096
#define Oo 512
#define NCTA 128
#define SMT 231424

__device__ float g_XW[(size_t)Bb * Tt * Gg];
__device__ char  g_Wf[(size_t)128 * 16 * 24576];   // 48MB recurrence A-frag images
__device__ char  g_Bf[2][2][131072];               // [layer][buf] h frags (hi|lo)
__device__ char  g_Apx[(size_t)33554432];          // x packed A-frags (hi|lo)
__device__ char  g_Ypk[(size_t)67108864];          // Y packed A-frags (hi|lo)
__device__ char  g_Bx [(size_t)8388608];           // Wx0 packed B-frags
__device__ char  g_Bd [(size_t)2097152];           // Wd  packed B-frags
__device__ unsigned g_arrive[NCTA];
__device__ unsigned g_go;

// ---------------- helpers ----------------------------------------------------
__device__ __forceinline__ unsigned smem_u32(const void* p) {
    unsigned a;
    asm("{ .reg .u64 t; cvta.to.shared.u64 t, %1; cvt.u32.u64 %0, t; }"
        : "=r"(a) : "l"(p));
    return a;
}
__device__ __forceinline__ void st_rel(unsigned* p, unsigned v) {
    asm volatile("st.release.gpu.u32 [%0],%1;" :: "l"(p), "r"(v) : "memory");
}
__device__ __forceinline__ unsigned ld_acq(const unsigned* p) {
    unsigned v; asm volatile("ld.acquire.gpu.u32 %0,[%1];" : "=r"(v) : "l"(p) : "memory");
    return v;
}
__device__ __forceinline__ void cp16(unsigned d, const char* s) {
    asm volatile("cp.async.cg.shared.global [%0],[%1],16;" :: "r"(d), "l"(s) : "memory");
}
#define CPC  asm volatile("cp.async.commit_group;" ::: "memory")
#define CPW0 asm volatile("cp.async.wait_group 0;" ::: "memory")
#define CPW1 asm volatile("cp.async.wait_group 1;" ::: "memory")
#define CPW3 asm volatile("cp.async.wait_group 3;" ::: "memory")
#define PAIRBAR(id) asm volatile("bar.sync %0, 64;" :: "r"(id) : "memory")
__device__ __forceinline__ void wpf(unsigned dst, const char* src, int lane) {
    asm volatile("cp.async.cg.shared.global [%0],[%1],16;\n\t"
                 "cp.async.cg.shared.global [%2],[%3],16;\n\t"
                 "cp.async.commit_group;"
                 :: "r"(dst + lane * 16), "l"(src + lane * 16),
                    "r"(dst + 512 + lane * 16), "l"(src + 512 + lane * 16)
                 : "memory");
}
__device__ __forceinline__ void mmabf(float* d, const unsigned* a, unsigned b0, unsigned b1) {
    asm volatile("mma.sync.aligned.m16n8k16.row.col.f32.bf16.bf16.f32 "
                 "{%0,%1,%2,%3},{%4,%5,%6,%7},{%8,%9},{%0,%1,%2,%3};"
                 : "+f"(d[0]), "+f"(d[1]), "+f"(d[2]), "+f"(d[3])
                 : "r"(a[0]), "r"(a[1]), "r"(a[2]), "r"(a[3]), "r"(b0), "r"(b1));
}
__device__ __forceinline__ void ldsA(unsigned sa, unsigned* ah, unsigned* al) {
    asm volatile("ld.shared.v4.b32 {%0,%1,%2,%3},[%4];"
        : "=r"(ah[0]), "=r"(ah[1]), "=r"(ah[2]), "=r"(ah[3]) : "r"(sa));
    asm volatile("ld.shared.v4.b32 {%0,%1,%2,%3},[%4];"
        : "=r"(al[0]), "=r"(al[1]), "=r"(al[2]), "=r"(al[3]) : "r"(sa + 16));
}
__device__ __forceinline__ float sig_(float x) { return 1.f / (1.f + __expf(-x)); }
__device__ __forceinline__ float tanh_(float x) {
    float xx = fminf(fmaxf(x, -15.f), 15.f);
    float e = __expf(-2.f * xx);
    return (1.f - e) / (1.f + e);
}
__device__ __forceinline__ void split2(float w0, float w1, unsigned &hp, unsigned &lp) {
    __nv_bfloat16 h0 = __float2bfloat16(w0), h1 = __float2bfloat16(w1);
    __nv_bfloat16 l0 = __float2bfloat16(w0 - __bfloat162float(h0));
    __nv_bfloat16 l1 = __float2bfloat16(w1 - __bfloat162float(h1));
    hp = (unsigned)*(unsigned short*)&h0 | ((unsigned)*(unsigned short*)&h1 << 16);
    lp = (unsigned)*(unsigned short*)&l0 | ((unsigned)*(unsigned short*)&l1 << 16);
}

__global__ void init_state() {
    int i = blockIdx.x * blockDim.x + threadIdx.x;
    uint4* bf = reinterpret_cast<uint4*>(&g_Bf[0][0][0]);
    if (i < 32768) bf[i] = make_uint4(0, 0, 0, 0);
    if (i < NCTA) g_arrive[i] = 0;
    if (i == 0) g_go = 0;
}

// ---------------- pack: recurrence W -> A-frag images (proven) ---------------
__global__ void pack_hmma(const float* __restrict__ W0, const float* __restrict__ W1,
                          const float* __restrict__ W2)
{
    unsigned id = blockIdx.x * blockDim.x + threadIdx.x;
    int reg = id & 3, lane = (id >> 2) & 31, tile = (id >> 7) & 7;
    int mh = (id >> 10) & 1, kc = (id >> 11) & 7;
    unsigned rm = id >> 14;
    int mat = rm % 3, cta = (int)(rm / 3);
    int r = lane >> 2, cq = (lane & 3) * 2;
    int m = mh * 16 + r + (reg & 1) * 8;
    int k = kc * 128 + tile * 16 + cq + ((reg >> 1) & 1) * 8;
    int col = (m >> 3) * Hh + cta * 8 + (m & 7);
    const float* W = (mat == 0) ? W0 : ((mat == 1) ? W1 : W2);
    unsigned hp, lp;
    split2(W[(size_t)k * Gg + col], W[(size_t)(k + 1) * Gg + col], hp, lp);
    int blk = (mat == 2) ? (16 + tile) : (tile * 2 + mat);
    size_t base = ((size_t)cta * 16 + (size_t)(kc * 2 + mh)) * 24576
                  + (size_t)blk * 1024 + (size_t)(lane * 32);
    *(unsigned*)(g_Wf + base + reg * 4) = hp;
    *(unsigned*)(g_Wf + base + 16 + reg * 4) = lp;
}

// ---------------- pack: GEMM B [K,N] fp32 -> B-frag hi|lo images -------------
__global__ void pack_Bw(const float* __restrict__ B, char* __restrict__ dst,
                        int KT, int N)
{
    unsigned id = blockIdx.x * blockDim.x + threadIdx.x;
    int reg = id & 1, lane = (id >> 1) & 31, n8 = (id >> 6) & 7;
    unsigned i9 = id >> 9;
    int kt = (int)(i9 % (unsigned)KT), nblk = (int)(i9 / (unsigned)KT);
    int n = nblk * 64 + n8 * 8 + (lane >> 2);
    int k = kt * 16 + reg * 8 + (lane & 3) * 2;
    unsigned hp, lp;
    split2(B[(size_t)k * N + n], B[(size_t)(k + 1) * N + n], hp, lp);
    size_t base = ((size_t)(nblk * KT + kt) * 8 + n8) * 512 + (size_t)(lane * 16);
    *(unsigned*)(dst + base + reg * 4) = hp;
    *(unsigned*)(dst + base + 8 + reg * 4) = lp;
}

// ---------------- cvt: A [M,K] fp32 -> A-frag hi|lo images -------------------
__global__ void cvt_Ax(const float* __restrict__ A, char* __restrict__ dst,
                       int KT, int K)
{
    unsigned id = blockIdx.x * blockDim.x + threadIdx.x;
    int reg = id & 3, lane = (id >> 2) & 31, mf = (id >> 7) & 7;
    unsigned i10 = id >> 10;
    int kt = (int)(i10 % (unsigned)KT), mblk = (int)(i10 / (unsigned)KT);
    int m = mblk * 128 + mf * 16 + (lane >> 2) + (reg & 1) * 8;
    int k = kt * 16 + (lane & 3) * 2 + ((reg >> 1) & 1) * 8;
    unsigned hp, lp;
    split2(A[(size_t)m * K + k], A[(size_t)m * K + k + 1], hp, lp);
    size_t base = ((size_t)(mblk * KT + kt) * 8 + mf) * 1024 + (size_t)(lane * 32);
    *(unsigned*)(dst + base + reg * 4) = hp;
    *(unsigned*)(dst + base + 16 + reg * 4) = lp;
}

// ---------------- HMMA GEMM: C[M,N] = A@B + bias (proven R15) ----------------
__global__ void __launch_bounds__(256) hmma_gemm(
        const char* __restrict__ Apk, const char* __restrict__ Bpk,
        const float* __restrict__ bias, float* __restrict__ C, int KT, int N)
{
    __shared__ char As[2][8192];
    __shared__ char Bs[2][4096];
    const int tid = threadIdx.x, lane = tid & 31, wid = tid >> 5;
    const int mw = wid & 3, nw = wid >> 2;
    const int mblk = blockIdx.y, nblk = blockIdx.x;
    const char* Agp = Apk + (size_t)mblk * KT * 8192;
    const char* Bgp = Bpk + (size_t)nblk * KT * 4096;
    const unsigned sa0 = smem_u32(As[0]), sa1 = smem_u32(As[1]);
    const unsigned sb0 = smem_u32(Bs[0]), sb1 = smem_u32(Bs[1]);

    float acc[2][4][4];
#pragma unroll
    for (int i = 0; i < 2; ++i)
#pragma unroll
        for (int j = 0; j < 4; ++j)
#pragma unroll
            for (int c = 0; c < 4; ++c) acc[i][j][c] = 0.f;

    cp16(sa0 + tid * 32, Agp + tid * 32);
    cp16(sa0 + tid * 32 + 16, Agp + tid * 32 + 16);
    cp16(sb0 + tid * 16, Bgp + tid * 16);
    CPC;

#pragma unroll 1
    for (int kt = 0; kt < KT; ++kt) {
        if (kt + 1 < KT) {
            unsigned da = (kt & 1) ? sa0 : sa1;
            unsigned db = (kt & 1) ? sb0 : sb1;
            const char* pa = Agp + (size_t)(kt + 1) * 8192;
            const char* pb = Bgp + (size_t)(kt + 1) * 4096;
            cp16(da + tid * 32, pa + tid * 32);
            cp16(da + tid * 32 + 16, pa + tid * 32 + 16);
            cp16(db + tid * 16, pb + tid * 16);
            CPC;
            CPW1;
        } else {
            CPW0;
        }
        __syncthreads();
        unsigned ab = (kt & 1) ? sa1 : sa0;
        unsigned bbs = (kt & 1) ? sb1 : sb0;
#pragma unroll
        for (int mi = 0; mi < 2; ++mi) {
            unsigned ah[4], al[4];
            ldsA(ab + (unsigned)((mw + mi * 4) * 1024 + lane * 32), ah, al);
#pragma unroll
            for (int n8 = 0; n8 < 4; ++n8) {
                unsigned bh0, bh1, bl0, bl1;
                asm volatile("ld.shared.v4.b32 {%0,%1,%2,%3},[%4];"
                    : "=r"(bh0), "=r"(bh1), "=r"(bl0), "=r"(bl1)
                    : "r"(bbs + (unsigned)((nw * 4 + n8) * 512 + lane * 16)));
                mmabf(acc[mi][n8], ah, bh0, bh1);
                mmabf(acc[mi][n8], al, bh0, bh1);
                mmabf(acc[mi][n8], ah, bl0, bl1);
            }
        }
        __syncthreads();
    }

#pragma unroll
    for (int mi = 0; mi < 2; ++mi) {
        int m0 = mblk * 128 + (mw + mi * 4) * 16 + (lane >> 2);
#pragma unroll
        for (int n8 = 0; n8 < 4; ++n8) {
            int n0 = nblk * 64 + (nw * 4 + n8) * 8 + (lane & 3) * 2;
            float2 bv = *reinterpret_cast<const float2*>(&bias[n0]);
            *reinterpret_cast<float2*>(&C[(size_t)m0 * N + n0]) =
                make_float2(acc[mi][n8][0] + bv.x, acc[mi][n8][1] + bv.y);
            *reinterpret_cast<float2*>(&C[(size_t)(m0 + 8) * N + n0]) =
                make_float2(acc[mi][n8][2] + bv.x, acc[mi][n8][3] + bv.y);
        }
    }
}

__device__ __forceinline__ void grid_bar(unsigned target) {
    __syncthreads();
    const unsigned tid = threadIdx.x;
    if (tid == 0) { __threadfence(); st_rel(&g_arrive[blockIdx.x], target); }
    if (blockIdx.x == 0) {
        if (tid < NCTA) { while (ld_acq(&g_arrive[tid]) < target) {} }
        __syncthreads();
        if (tid == 0) st_rel(&g_go, target);
    }
    if (tid == 0) { while (ld_acq(&g_go) < target) {} }
    __syncthreads();
}

// ---------------- recurrence pieces -------------------------------------------
__device__ __forceinline__ void stage_slice(unsigned sb, const char* src,
                                            unsigned slice, int lt)
{
    const char* sp = src + slice;
#pragma unroll
    for (int i = 0; i < 16; ++i) {
        unsigned o = (unsigned)((i * 64 + lt) * 16);
        cp16(sb + slice + o, sp + o);
    }
    CPC;
}

// fused mat0+mat1: 16 blocks; 4-slot W ring, prefetch distance 3
__device__ __forceinline__ void run_fused(float (&acc)[4][4], float (&accB)[4][4],
    bool a0, bool a1, int &cb, unsigned wring, const char* __restrict__ wg,
    unsigned sb, int kc, int lane)
{
    unsigned bf[4][4];
#pragma unroll 1
    for (int blk = 0; blk < 16; ++blk) {
        int pb = cb + 3; if (pb >= 24) pb -= 24;
        wpf(wring + (unsigned)((pb & 3) * 1024), wg + (size_t)pb * 1024, lane);
        CPW3;
        __syncwarp();
        int kt = kc * 8 + (blk >> 1);
        unsigned sa = wring + (unsigned)((cb & 3) * 1024 + lane * 32);
        if ((blk & 1) == 0) {
            if (a0 | a1) {
#pragma unroll
                for (int n8 = 0; n8 < 4; ++n8)
                    asm volatile("ld.shared.v4.b32 {%0,%1,%2,%3},[%4];"
                        : "=r"(bf[n8][0]), "=r"(bf[n8][1]),
                          "=r"(bf[n8][2]), "=r"(bf[n8][3])
                        : "r"(sb + (unsigned)(((kt * 4 + n8) * 32 + lane) * 16)));
            }
            if (a0) {
                unsigned ah[4], al[4];
                ldsA(sa, ah, al);
#pragma unroll
                for (int n8 = 0; n8 < 4; ++n8) {
                    mmabf(acc[n8], ah, bf[n8][0], bf[n8][1]);
                    mmabf(acc[n8], al, bf[n8][0], bf[n8][1]);
                    mmabf(acc[n8], ah, bf[n8][2], bf[n8][3]);
                }
            }
        } else if (a1) {
            unsigned ah[4], al[4];
            ldsA(sa, ah, al);
#pragma unroll
            for (int n8 = 0; n8 < 4; ++n8) {
                mmabf(accB[n8], ah, bf[n8][0], bf[n8][1]);
                mmabf(accB[n8], al, bf[n8][0], bf[n8][1]);
                mmabf(accB[n8], ah, bf[n8][2], bf[n8][3]);
            }
        }
        ++cb; if (cb >= 24) cb = 0;
    }
}

__device__ __forceinline__ void run_mat2(float (&accB)[4][4], bool a2, int &cb,
    unsigned wring, const char* __restrict__ wg, unsigned sb, int kc, int lane)
{
#pragma unroll 1
    for (int tile = 0; tile < 8; ++tile) {
        int pb = cb + 3; if (pb >= 24) pb -= 24;
        wpf(wring + (unsigned)((pb & 3) * 1024), wg + (size_t)pb * 1024, lane);
        CPW3;
        __syncwarp();
        if (a2) {
            int kt = kc * 8 + tile;
            unsigned sa = wring + (unsigned)((cb & 3) * 1024 + lane * 32);
            unsigned ah[4], al[4];
            ldsA(sa, ah, al);
#pragma unroll
            for (int n8 = 0; n8 < 4; ++n8) {
                unsigned b0, b1, b2, b3;
                asm volatile("ld.shared.v4.b32 {%0,%1,%2,%3},[%4];"
                    : "=r"(b0), "=r"(b1), "=r"(b2), "=r"(b3)
                    : "r"(sb + (unsigned)(((kt * 4 + n8) * 32 + lane) * 16)));
                mmabf(accB[n8], ah, b0, b1);
                mmabf(accB[n8], al, b0, b1);
                mmabf(accB[n8], ah, b2, b3);
            }
        }
        ++cb; if (cb >= 24) cb = 0;
    }
}

// red: stride 34 (float2-aligned, <=2-way conflicts on gate reads)
__device__ __forceinline__ void store_redH(float* red, float (&acc)[4][4],
                                           int kc, int mh, int lane)
{
    int r = lane >> 2, cq = (lane & 3) * 2;
#pragma unroll
    for (int n8 = 0; n8 < 4; ++n8) {
        int b = n8 * 8 + cq;
        int c = mh * 16 + r;
        *reinterpret_cast<float2*>(&red[kc * 1088 + c * 34 + b]) =
            make_float2(acc[n8][0], acc[n8][1]);
        *reinterpret_cast<float2*>(&red[kc * 1088 + (c + 8) * 34 + b]) =
            make_float2(acc[n8][2], acc[n8][3]);
    }
}

__device__ __forceinline__ void wr_frag(char* bb, int k, int b, float h) {
    int kt = k >> 4, kin = k & 15;
    int reg = kin >> 3, quad = (kin >> 1) & 3, half = kin & 1;
    unsigned off = (unsigned)((((kt * 4 + (b >> 3)) * 32) + (b & 7) * 4 + quad) * 16
                              + reg * 4 + half * 2);
    __nv_bfloat16 hh = __float2bfloat16(h);
    __nv_bfloat16 hl = __float2bfloat16(h - __bfloat162float(hh));
    *(__nv_bfloat16*)(bb + off) = hh;
    *(__nv_bfloat16*)(bb + off + 8) = hl;
}

__device__ __forceinline__ void wr_Ypk(int m, int k, float h) {
    int mblk = m >> 7, mi = m & 127, mf = mi >> 4, r16 = mi & 15;
    int kt = k >> 4, ki = k & 15;
    int reg = (r16 >> 3) | ((ki >> 3) << 1);
    int ln = (r16 & 7) * 4 + ((ki & 7) >> 1);
    size_t base = ((size_t)(mblk * 64 + kt) * 8 + mf) * 1024 + (size_t)(ln * 32);
    __nv_bfloat16 hh = __float2bfloat16(h);
    __nv_bfloat16 hl = __float2bfloat16(h - __bfloat162float(hh));
    char* p = g_Ypk + base + reg * 4 + (ki & 1) * 2;
    *(__nv_bfloat16*)p = hh;
    *(__nv_bfloat16*)(p + 16) = hl;
}

// ---------------- persistent 2-layer LSTM recurrence (HMMA) ------------------
// SMEM: [0,128K) B  [131072,196608) W ring 16x4KB  [196608,231424) red
__global__ void __launch_bounds__(512, 1) lstm_hm4(const float* __restrict__ b1v)
{
    extern __shared__ char smc[];
    float* red = reinterpret_cast<float*>(smc + 196608);
    const unsigned sb = smem_u32(smc);

    const int tid = threadIdx.x, lane = tid & 31, wid = tid >> 5;
    const int kc = wid >> 1, mh = wid & 1;
    const int lt = tid & 63;
    const unsigned slice = (unsigned)(kc * 16384);
    const int cta = blockIdx.x, jbase = cta * 8;
    const unsigned wring = sb + 131072u + (unsigned)(wid * 4096);
    const char* wg = g_Wf + ((size_t)cta * 16 + (size_t)(kc * 2 + mh)) * 24576;

    const int gb = tid >> 3, gj = tid & 7;
    float c0s = 0.f, c1s = 0.f;
    float bias1[4];
    if (tid < 256) {
#pragma unroll
        for (int g = 0; g < 4; ++g) bias1[g] = b1v[g * Hh + jbase + gj];
    }

    int cb = 0;
    wpf(wring, wg, lane);
    wpf(wring + 1024, wg + 1024, lane);
    wpf(wring + 2048, wg + 2048, lane);

    for (int s = 0; s <= Tt; ++s) {
        const int rb = (s + 1) & 1;
        const int wb = s & 1;

        stage_slice(sb, g_Bf[0][rb], slice, lt);

        float xw[4];
        if (tid < 256 && s < Tt) {
#pragma unroll
            for (int g = 0; g < 4; ++g)
                xw[g] = __ldcg(&g_XW[((size_t)gb * Tt + s) * Gg + g * Hh + jbase + gj]);
        }
        CPW0;
        PAIRBAR(kc + 1);

        float acc[4][4], accB[4][4];
#pragma unroll
        for (int i = 0; i < 4; ++i)
#pragma unroll
            for (int j = 0; j < 4; ++j) { acc[i][j] = 0.f; accB[i][j] = 0.f; }

        run_fused(acc, accB, s < Tt, s > 0, cb, wring, wg, sb, kc, lane);
        if (s < Tt) store_redH(red, acc, kc, mh, lane);
        __syncthreads();                              // #1: red ready, B(h0) free

        stage_slice(sb, g_Bf[1][rb], slice, lt);      // h1 slice under reduction

        float z0[4];
        if (tid < 256 && s < Tt) {
#pragma unroll
            for (int g = 0; g < 4; ++g) {
                float t = xw[g];
#pragma unroll
                for (int kk = 0; kk < 8; ++kk)
                    t += red[kk * 1088 + (g * 8 + gj) * 34 + gb];
                z0[g] = t;
            }
        }
        CPW0;
        __syncthreads();                              // #2: slices visible, z0 read

        run_mat2(accB, s > 0, cb, wring, wg, sb, kc, lane);
        if (s > 0) store_redH(red, accB, kc, mh, lane);
        __syncthreads();                              // #3: red(mat2) ready

        if (tid < 256) {
            if (s < Tt) {
                float I = sig_(z0[0]), F = sig_(z0[1]);
                float G = tanh_(z0[2]), O = sig_(z0[3]);
                c0s = F * c0s + I * G;
                float h = O * tanh_(c0s);
                wr_frag(g_Bf[0][wb], jbase + gj, gb, h);
            }
            if (s > 0) {
                float z1[4];
#pragma unroll
                for (int g = 0; g < 4; ++g) {
                    float t = bias1[g];
#pragma unroll
                    for (int kk = 0; kk < 8; ++kk)
                        t += red[kk * 1088 + (g * 8 + gj) * 34 + gb];
                    z1[g] = t;
                }
                float I = sig_(z1[0]), F = sig_(z1[1]);
                float G = tanh_(z1[2]), O = sig_(z1[3]);
                c1s = F * c1s + I * G;
                float h = O * tanh_(c1s);
                wr_frag(g_Bf[1][wb], jbase + gj, gb, h);
                wr_Ypk(gb * Tt + (s - 1), jbase + gj, h);
            }
        }
        grid_bar((unsigned)(s + 1));
    }
    CPW0;
}

// ---------------- launch ------------------------------------------------------
extern "C" void kernel_launch(void* const* d_in, const int* in_sizes, int n_in,
                              void* d_out, int out_size)
{
    const float* x   = (const float*)d_in[0];
    const float* Wx0 = (const float*)d_in[1];
    const float* Wh0 = (const float*)d_in[2];
    const float* b0v = (const float*)d_in[3];
    const float* Wx1 = (const float*)d_in[4];
    const float* Wh1 = (const float*)d_in[5];
    const float* b1v = (const float*)d_in[6];
    const float* Wd  = (const float*)d_in[7];
    const float* bdv = (const float*)d_in[8];
    float* out = (float*)d_out;

    float* xw;  cudaGetSymbolAddress((void**)&xw,  g_XW);
    char*  apx; cudaGetSymbolAddress((void**)&apx, g_Apx);
    char*  ypk; cudaGetSymbolAddress((void**)&ypk, g_Ypk);
    char*  bx;  cudaGetSymbolAddress((void**)&bx,  g_Bx);
    char*  bd;  cudaGetSymbolAddress((void**)&bd,  g_Bd);

    cudaFuncSetAttribute(lstm_hm4, cudaFuncAttributeMaxDynamicSharedMemorySize, SMT);

    init_state<<<64, 512>>>();
    pack_hmma<<<24576, 256>>>(Wh0, Wx1, Wh1);
    pack_Bw<<<4096, 256>>>(Wx0, bx, Dd / 16, Gg);
    pack_Bw<<<1024, 256>>>(Wd,  bd, Hh / 16, Oo);
    cvt_Ax<<<16384, 256>>>(x, apx, Dd / 16, Dd);

    // XW = x @ Wx0 + b0   [16384,4096]
    hmma_gemm<<<dim3(Gg / 64, (Bb * Tt) / 128), 256>>>(apx, bx, b0v, xw,
                                                       Dd / 16, Gg);
    lstm_hm4<<<NCTA, 512, SMT>>>(b1v);

    // out = Y @ Wd + bd   [16384,512]
    hmma_gemm<<<dim3(Oo / 64, (Bb * Tt) / 128), 256>>>(ypk, bd, bdv, out,
                                                       Hh / 16, Oo);
}